// round 4
// baseline (speedup 1.0000x reference)
#include <cuda_runtime.h>
#include <cuda_bf16.h>

// Problem constants
#define BATCH 64
#define SEQ   1024
#define DIN   256
#define UNITS 512

// Recurrence partitioning: 8 batch-groups x 16 unit-slices = 128 CTAs
#define NGRP   8      // batch groups
#define GROWS  8      // batch rows per group
#define NSLICE 16     // unit slices
#define SU     32     // units per slice
#define KDIM   512    // contraction dim (= UNITS)

// Persistent-kernel global state (allowed: __device__ global arrays)
__device__ float g_hbuf[2][BATCH * UNITS];   // double-buffered hidden state (256 KB)
__device__ int   g_cnt[NGRP];                // per-group step counters

// ---------------------------------------------------------------------------
// Kernel 0: reset the step counters (graph replays must start clean)
// ---------------------------------------------------------------------------
__global__ void ltc_zero_cnt() {
    if (threadIdx.x < NGRP) g_cnt[threadIdx.x] = 0;
}

// ---------------------------------------------------------------------------
// Kernel 1: xW GEMM  C[65536,512] = A[65536,256] @ B[256,512], written to out.
// Classic 128x128 tile, BK=8, 256 threads, 8x8 microtile, float4 smem frags.
// ---------------------------------------------------------------------------
#define BM 128
#define BN 128
#define BK 8

__global__ __launch_bounds__(256) void ltc_xw_gemm(
    const float* __restrict__ A,   // [65536, 256]
    const float* __restrict__ B,   // [256, 512]
    float* __restrict__ C)         // [65536, 512]
{
    __shared__ float Asm[BK][BM];
    __shared__ float Bsm[BK][BN];

    const int tid = threadIdx.x;
    const int bm = blockIdx.y * BM;
    const int bn = blockIdx.x * BN;

    const int tx = tid & 15;       // 0..15 -> 8 output cols each
    const int ty = tid >> 4;       // 0..15 -> 8 output rows each

    // Loader indices
    const int arow = tid >> 1;          // 0..127
    const int acol = (tid & 1) * 4;     // 0 or 4
    const int brow = tid >> 5;          // 0..7
    const int bcol = (tid & 31) * 4;    // 0..124

    const float* Ap = A + (long)(bm + arow) * DIN + acol;
    const float* Bp = B + (long)brow * UNITS + bn + bcol;

    float acc[8][8];
#pragma unroll
    for (int i = 0; i < 8; i++)
#pragma unroll
        for (int j = 0; j < 8; j++) acc[i][j] = 0.0f;

    for (int k0 = 0; k0 < DIN; k0 += BK) {
        float4 av = *(const float4*)(Ap + k0);
        float4 bv = *(const float4*)(Bp + (long)k0 * UNITS);

        __syncthreads();
        Asm[acol + 0][arow] = av.x;
        Asm[acol + 1][arow] = av.y;
        Asm[acol + 2][arow] = av.z;
        Asm[acol + 3][arow] = av.w;
        *(float4*)&Bsm[brow][bcol] = bv;
        __syncthreads();

#pragma unroll
        for (int k = 0; k < BK; ++k) {
            float a[8], b[8];
            *(float4*)(a)     = *(const float4*)&Asm[k][ty * 8];
            *(float4*)(a + 4) = *(const float4*)&Asm[k][ty * 8 + 4];
            *(float4*)(b)     = *(const float4*)&Bsm[k][tx * 8];
            *(float4*)(b + 4) = *(const float4*)&Bsm[k][tx * 8 + 4];
#pragma unroll
            for (int i = 0; i < 8; i++)
#pragma unroll
                for (int j = 0; j < 8; j++)
                    acc[i][j] = fmaf(a[i], b[j], acc[i][j]);
        }
    }

#pragma unroll
    for (int i = 0; i < 8; i++) {
        float* crow = C + (long)(bm + ty * 8 + i) * UNITS + bn + tx * 8;
        float4 v0 = make_float4(acc[i][0], acc[i][1], acc[i][2], acc[i][3]);
        float4 v1 = make_float4(acc[i][4], acc[i][5], acc[i][6], acc[i][7]);
        *(float4*)(crow)     = v0;
        *(float4*)(crow + 4) = v1;
    }
}

// ---------------------------------------------------------------------------
// Kernel 2: persistent LTC recurrence.
// Grid = 128 CTAs: blockIdx.x = g*16 + s  (g: batch group, s: unit slice).
// Each CTA holds U[:, 32s:32s+32] (fp32, 64 KB) in smem for the whole run.
// Per step: read full h[g-rows, 512] from L2-staged global double buffer,
// compute its 8x32 output slice, write it back, bump the group counter.
// Thread layout (256 threads): compute phase (u = tid&31, kg = tid>>5)
//   -> partial dot over k in [64*kg, 64*kg+64) for all 8 rows, U reg-reused.
// Combine phase (r = tid>>5, u = tid&31) sums the 8 partials + epilogue.
// ---------------------------------------------------------------------------
#define REC_THREADS 256
// smem floats: U slice + h + reduction + b + inv_tau
#define SMEM_U   (KDIM * SU)       // 16384
#define SMEM_H   (GROWS * KDIM)    // 4096
#define SMEM_R   (8 * GROWS * SU)  // 2048
#define SMEM_FLOATS (SMEM_U + SMEM_H + SMEM_R + SU + SU)
#define SMEM_BYTES  (SMEM_FLOATS * 4)

extern __shared__ float s_mem[];

__global__ __launch_bounds__(REC_THREADS, 1) void ltc_recur(
    const float* __restrict__ Umat,  // [512, 512] row-major [k][u]
    const float* __restrict__ bvec,  // [512]
    const float* __restrict__ tau,   // [512]
    float* __restrict__ out)         // [64, 1024, 512]; holds xW on entry
{
    float* Usm = s_mem;               // [k][u']  k*SU + u
    float* hsm = Usm + SMEM_U;        // [r][k]   r*KDIM + k
    float* red = hsm + SMEM_H;        // [kg][r][u]  kg*256 + r*32 + u
    float* bs  = red + SMEM_R;        // [SU]
    float* its = bs + SU;             // [SU]

    const int tid = threadIdx.x;
    const int g   = blockIdx.x >> 4;   // batch group 0..7
    const int s   = blockIdx.x & 15;   // unit slice 0..15
    const int u0  = s * SU;

    // Load U slice (coalesced: 32 consecutive units per k-row)
    for (int i = tid; i < SMEM_U; i += REC_THREADS) {
        int k = i >> 5, uu = i & 31;
        Usm[i] = Umat[(long)k * UNITS + u0 + uu];
    }
    if (tid < SU) {
        bs[tid]  = bvec[u0 + tid];
        its[tid] = 1.0f / tau[u0 + tid];
    }
    for (int i = tid; i < SMEM_H; i += REC_THREADS) hsm[i] = 0.0f;
    __syncthreads();

    const int u  = tid & 31;     // unit within slice (both phases)
    const int kg = tid >> 5;     // k-group (compute) / row (combine)
    const float it_u = its[u];
    const float b_u  = bs[u];
    const int kbase = kg * 64;

    for (int t = 0; t < SEQ; ++t) {
        if (t > 0) {
            // Wait for all 16 CTAs of this group to finish step t-1
            if (tid == 0) {
                const int target = 16 * t;
                while (atomicAdd(&g_cnt[g], 0) < target) { }
            }
            __syncthreads();
            // Load full h_{t-1} for this group's 8 rows (L2, .cg to bypass L1)
            const float4* src = (const float4*)&g_hbuf[t & 1][(long)g * GROWS * UNITS];
            float4* dst = (float4*)hsm;
            for (int i = tid; i < SMEM_H / 4; i += REC_THREADS)
                dst[i] = __ldcg(&src[i]);
            __syncthreads();
        }

        // Partial dot products: this thread covers k in [kbase, kbase+64)
        float acc[GROWS];
#pragma unroll
        for (int r = 0; r < GROWS; r++) acc[r] = 0.0f;

#pragma unroll
        for (int kk = 0; kk < 64; kk += 4) {
            const float uv0 = Usm[(kbase + kk + 0) * SU + u];
            const float uv1 = Usm[(kbase + kk + 1) * SU + u];
            const float uv2 = Usm[(kbase + kk + 2) * SU + u];
            const float uv3 = Usm[(kbase + kk + 3) * SU + u];
#pragma unroll
            for (int r = 0; r < GROWS; r++) {
                float4 h4 = *(const float4*)&hsm[r * KDIM + kbase + kk];
                float a = acc[r];
                a = fmaf(h4.x, uv0, a);
                a = fmaf(h4.y, uv1, a);
                a = fmaf(h4.z, uv2, a);
                a = fmaf(h4.w, uv3, a);
                acc[r] = a;
            }
        }
#pragma unroll
        for (int r = 0; r < GROWS; r++)
            red[kg * (GROWS * SU) + r * SU + u] = acc[r];
        __syncthreads();

        // Combine + epilogue: thread -> (row r = kg, unit u)
        {
            const int r = kg;
            float dot = 0.0f;
#pragma unroll
            for (int q = 0; q < 8; q++)
                dot += red[q * (GROWS * SU) + r * SU + u];
            const float hp = hsm[r * KDIM + u0 + u];
            const long oidx = ((long)(g * GROWS + r) * SEQ + t) * UNITS + u0 + u;
            const float xw = out[oidx];
            const float hn = hp + it_u * (xw + dot + b_u - hp);
            out[oidx] = hn;
            g_hbuf[(t + 1) & 1][(long)(g * GROWS + r) * UNITS + u0 + u] = hn;
        }
        __threadfence();
        __syncthreads();
        if (tid == 0 && t < SEQ - 1) atomicAdd(&g_cnt[g], 1);
    }
}

// ---------------------------------------------------------------------------
// Launch
// ---------------------------------------------------------------------------
extern "C" void kernel_launch(void* const* d_in, const int* in_sizes, int n_in,
                              void* d_out, int out_size) {
    (void)in_sizes; (void)n_in; (void)out_size;
    const float* x   = (const float*)d_in[0];   // [64,1024,256]
    const float* W   = (const float*)d_in[1];   // [256,512]
    const float* U   = (const float*)d_in[2];   // [512,512]
    const float* b   = (const float*)d_in[3];   // [512]
    const float* tau = (const float*)d_in[4];   // [512]
    float* out = (float*)d_out;                 // [64,1024,512]

    // 1) xW -> out
    dim3 ggrid(UNITS / BN, (BATCH * SEQ) / BM);  // (4, 512)
    ltc_xw_gemm<<<ggrid, 256>>>(x, W, out);

    // 2) reset persistent counters (fresh every graph replay)
    ltc_zero_cnt<<<1, 32>>>();

    // 3) persistent recurrence (90 KB dynamic smem, 128 co-resident CTAs)
    cudaFuncSetAttribute(ltc_recur, cudaFuncAttributeMaxDynamicSharedMemorySize,
                         SMEM_BYTES);
    ltc_recur<<<NGRP * NSLICE, REC_THREADS, SMEM_BYTES>>>(U, b, tau, out);
}